// round 15
// baseline (speedup 1.0000x reference)
#include <cuda_runtime.h>
#include <cuda_bf16.h>
#include <cstdint>
#include <math.h>

#define BB 2
#define CC 128
#define NH 4
#define DH 32
#define NT 4096
#define SCALE_F 10.0f

#define NF 640
#define NFB 5
#define NE 40
#define TS 272
#define GSS 1296
#define JSPLIT 16

static __device__ __nv_bfloat16 g_qb[BB * CC * NT];
static __device__ __nv_bfloat16 g_kb[BB * CC * NT];
static __device__ __nv_bfloat16 g_vb[BB * CC * NT];
static __device__ float g_att[BB * CC * NT];
static __device__ float g_colsum[BB * CC];
static __device__ float g_nsq[2][BB * CC][32];
static __device__ __nv_bfloat16 g_G2[8 * JSPLIT * NE * NF];   // bf16 partials
static __device__ __nv_bfloat16 g_Gb[8 * NE * NF];

// ---------------------------------------------------------------- helpers ----
__device__ __forceinline__ uint32_t smem_u32(const void* p) {
    uint32_t a;
    asm("{ .reg .u64 t; cvta.to.shared.u64 t, %1; cvt.u32.u64 %0, t; }"
        : "=r"(a) : "l"(p));
    return a;
}
__device__ __forceinline__ uint32_t packbf(float a, float b) {
    uint32_t r;
    asm("cvt.rn.bf16x2.f32 %0, %2, %1;" : "=r"(r) : "f"(a), "f"(b));
    return r;
}
__device__ __forceinline__ uint32_t bffma2(uint32_t a, uint32_t b, uint32_t c) {
    uint32_t d;
    asm("fma.rn.bf16x2 %0, %1, %2, %3;" : "=r"(d) : "r"(a), "r"(b), "r"(c));
    return d;
}
__device__ __forceinline__ void ldsm4(uint32_t& r0, uint32_t& r1, uint32_t& r2,
                                      uint32_t& r3, uint32_t addr) {
    asm volatile("ldmatrix.sync.aligned.m8n8.x4.shared.b16 {%0,%1,%2,%3}, [%4];"
                 : "=r"(r0), "=r"(r1), "=r"(r2), "=r"(r3) : "r"(addr));
}
__device__ __forceinline__ void ldsm4t(uint32_t& r0, uint32_t& r1, uint32_t& r2,
                                       uint32_t& r3, uint32_t addr) {
    asm volatile("ldmatrix.sync.aligned.m8n8.x4.trans.shared.b16 {%0,%1,%2,%3}, [%4];"
                 : "=r"(r0), "=r"(r1), "=r"(r2), "=r"(r3) : "r"(addr));
}
__device__ __forceinline__ void mma16816(float* c, uint32_t a0, uint32_t a1,
                                         uint32_t a2, uint32_t a3,
                                         uint32_t b0, uint32_t b1) {
    asm volatile(
        "mma.sync.aligned.m16n8k16.row.col.f32.bf16.bf16.f32 "
        "{%0,%1,%2,%3}, {%4,%5,%6,%7}, {%8,%9}, {%0,%1,%2,%3};"
        : "+f"(c[0]), "+f"(c[1]), "+f"(c[2]), "+f"(c[3])
        : "r"(a0), "r"(a1), "r"(a2), "r"(a3), "r"(b0), "r"(b1));
}
__device__ __forceinline__ void cp16(uint32_t dst, const void* src) {
    asm volatile("cp.async.cg.shared.global [%0], [%1], 16;"
                 :: "r"(dst), "l"(src) : "memory");
}

__device__ __forceinline__ void fdec(int f, int& a, int& b) {
    if (f < 32) { a = f; b = 32; }
    else if (f < 560) {
        int p = f - 32, aa = 0;
        while (p >= 32 - aa) { p -= 32 - aa; ++aa; }
        a = aa; b = aa + p;
    } else { a = 33; b = 33; }
}
__device__ __forceinline__ float fweight(int f) {
    if (f < 32) return 1.0f;
    if (f >= 560) return 0.0f;
    int a, b; fdec(f, a, b);
    return (a == b) ? 0.5f : 1.0f;
}
__device__ __forceinline__ void build_lut(uint32_t* lut, int tid) {
    for (int f = tid; f < NF; f += 256) {
        int a, b; fdec(f, a, b);
        lut[f] = (uint32_t)a | ((uint32_t)b << 8);
    }
}

// ============================= projections ===================================
#define PW_STRIDE 272
#define PB64_STRIDE 144

__global__ void __launch_bounds__(256, 2)
proj_qkv_mma(const float* __restrict__ x, const float* __restrict__ cx,
             const float* __restrict__ Wq, const float* __restrict__ bq,
             const float* __restrict__ Wk, const float* __restrict__ bk,
             const float* __restrict__ Wv, const float* __restrict__ bv)
{
    extern __shared__ unsigned char psm[];
    unsigned char* Wh = psm;
    unsigned char* Bh = psm + 128 * PW_STRIDE;

    const int tid = threadIdx.x, w = tid >> 5, lane = tid & 31;
    const int n0 = blockIdx.x * 128, b = blockIdx.y, wh = blockIdx.z;
    const float *W, *bias, *inb;
    if (wh == 0)      { W = Wq; bias = bq; inb = x  + (size_t)b * CC * NT; }
    else if (wh == 1) { W = Wk; bias = bk; inb = cx + (size_t)b * CC * NT; }
    else              { W = Wv; bias = bv; inb = cx + (size_t)b * CC * NT; }

#pragma unroll
    for (int it = 0; it < 16; ++it) {
        const int idx = tid + it * 256;
        const int m = idx >> 5, c4 = idx & 31;
        float4 ww = *(const float4*)(W + m * 128 + c4 * 4);
        *(uint2*)(Wh + m * PW_STRIDE + c4 * 8) =
            make_uint2(packbf(ww.x, ww.y), packbf(ww.z, ww.w));
    }
#pragma unroll
    for (int it = 0; it < 16; ++it) {
        const int idx = tid + it * 256;
        const int c = idx >> 5, c4 = idx & 31;
        float4 v = *(const float4*)(inb + (size_t)c * NT + n0 + c4 * 4);
        *(uint2*)(Bh + c * PW_STRIDE + c4 * 8) =
            make_uint2(packbf(v.x, v.y), packbf(v.z, v.w));
    }
    __syncthreads();

    const uint32_t uWh = smem_u32(Wh), uBh = smem_u32(Bh);
    uint32_t A[8][4];
    {
        const int q = lane >> 3, r = lane & 7;
#pragma unroll
        for (int ks = 0; ks < 8; ++ks)
            ldsm4(A[ks][0], A[ks][1], A[ks][2], A[ks][3],
                  uWh + (w * 16 + (q & 1) * 8 + r) * PW_STRIDE
                      + (ks * 16 + (q >> 1) * 8) * 2);
    }
    const int g = lane >> 2, tq = lane & 3;
    const int m0 = w * 16 + g, m1 = m0 + 8;
    const float bb0 = bias[m0], bb1 = bias[m1];
    float sq0 = 0.f, sq1 = 0.f;

    __nv_bfloat16* qkout = (wh == 0 ? g_qb : g_kb) + (size_t)(b * CC) * NT;
    __nv_bfloat16* vout  = g_vb + (size_t)(b * CC) * NT;

#pragma unroll
    for (int nh = 0; nh < 2; ++nh) {
        float acc[8][4];
#pragma unroll
        for (int nt = 0; nt < 8; ++nt)
            acc[nt][0] = acc[nt][1] = acc[nt][2] = acc[nt][3] = 0.f;
#pragma unroll
        for (int nt = 0; nt < 8; ++nt) {
            const uint32_t colb = nh * 128 + nt * 16;
#pragma unroll
            for (int cb = 0; cb < 4; ++cb) {
                uint32_t b0, b1, b2, b3;
                ldsm4t(b0, b1, b2, b3, uBh + (cb * 32 + lane) * PW_STRIDE + colb);
                mma16816(acc[nt], A[2*cb][0], A[2*cb][1], A[2*cb][2], A[2*cb][3], b0, b1);
                mma16816(acc[nt], A[2*cb+1][0], A[2*cb+1][1], A[2*cb+1][2], A[2*cb+1][3], b2, b3);
            }
        }
#pragma unroll
        for (int nt = 0; nt < 8; ++nt) {
            const int n = n0 + nh * 64 + nt * 8 + tq * 2;
            const float v0 = acc[nt][0] + bb0, v1 = acc[nt][1] + bb0;
            const float v2 = acc[nt][2] + bb1, v3 = acc[nt][3] + bb1;
            if (wh == 2) {
                *(uint32_t*)(vout + (size_t)m0 * NT + n) = packbf(v0, v1);
                *(uint32_t*)(vout + (size_t)m1 * NT + n) = packbf(v2, v3);
            } else {
                *(uint32_t*)(qkout + (size_t)m0 * NT + n) = packbf(v0, v1);
                *(uint32_t*)(qkout + (size_t)m1 * NT + n) = packbf(v2, v3);
                sq0 += v0 * v0 + v1 * v1;
                sq1 += v2 * v2 + v3 * v3;
            }
        }
    }
    if (wh < 2) {
        sq0 += __shfl_xor_sync(0xffffffffu, sq0, 1);
        sq0 += __shfl_xor_sync(0xffffffffu, sq0, 2);
        sq1 += __shfl_xor_sync(0xffffffffu, sq1, 1);
        sq1 += __shfl_xor_sync(0xffffffffu, sq1, 2);
        if (tq == 0) {
            g_nsq[wh][b * CC + m0][blockIdx.x] = sq0;
            g_nsq[wh][b * CC + m1][blockIdx.x] = sq1;
        }
    }
}

__global__ void __launch_bounds__(256, 2)
proj_out_mma(const float* __restrict__ Wo, const float* __restrict__ bo,
             float* __restrict__ out)
{
    extern __shared__ unsigned char psm[];
    unsigned char* Wh = psm;
    unsigned char* Wl = psm + 128 * PW_STRIDE;
    unsigned char* Bh = Wl + 128 * PW_STRIDE;
    unsigned char* Bl = Bh + 128 * PB64_STRIDE;

    const int tid = threadIdx.x, w = tid >> 5, lane = tid & 31;
    const int n0 = blockIdx.x * 64, b = blockIdx.y;
    const float* inb = g_att + (size_t)b * CC * NT;

#pragma unroll
    for (int it = 0; it < 16; ++it) {
        const int idx = tid + it * 256;
        const int m = idx >> 5, c4 = idx & 31;
        float4 ww = *(const float4*)(Wo + m * 128 + c4 * 4);
        uint32_t h0 = packbf(ww.x, ww.y), h1 = packbf(ww.z, ww.w);
        float l0 = ww.x - __uint_as_float(h0 << 16);
        float l1 = ww.y - __uint_as_float(h0 & 0xffff0000u);
        float l2 = ww.z - __uint_as_float(h1 << 16);
        float l3 = ww.w - __uint_as_float(h1 & 0xffff0000u);
        *(uint2*)(Wh + m * PW_STRIDE + c4 * 8) = make_uint2(h0, h1);
        *(uint2*)(Wl + m * PW_STRIDE + c4 * 8) =
            make_uint2(packbf(l0, l1), packbf(l2, l3));
    }
#pragma unroll
    for (int it = 0; it < 8; ++it) {
        const int idx = tid + it * 256;
        const int c = idx >> 4, c4 = idx & 15;
        float4 v = *(const float4*)(inb + (size_t)c * NT + n0 + c4 * 4);
        uint32_t h0 = packbf(v.x, v.y), h1 = packbf(v.z, v.w);
        float l0 = v.x - __uint_as_float(h0 << 16);
        float l1 = v.y - __uint_as_float(h0 & 0xffff0000u);
        float l2 = v.z - __uint_as_float(h1 << 16);
        float l3 = v.w - __uint_as_float(h1 & 0xffff0000u);
        *(uint2*)(Bh + c * PB64_STRIDE + c4 * 8) = make_uint2(h0, h1);
        *(uint2*)(Bl + c * PB64_STRIDE + c4 * 8) =
            make_uint2(packbf(l0, l1), packbf(l2, l3));
    }
    __syncthreads();

    const uint32_t uWh = smem_u32(Wh), uWl = smem_u32(Wl);
    const uint32_t uBh = smem_u32(Bh), uBl = smem_u32(Bl);
    uint32_t Ah[8][4], Al[8][4];
    {
        const int q = lane >> 3, r = lane & 7;
#pragma unroll
        for (int ks = 0; ks < 8; ++ks) {
            const uint32_t off = (w * 16 + (q & 1) * 8 + r) * PW_STRIDE
                               + (ks * 16 + (q >> 1) * 8) * 2;
            ldsm4(Ah[ks][0], Ah[ks][1], Ah[ks][2], Ah[ks][3], uWh + off);
            ldsm4(Al[ks][0], Al[ks][1], Al[ks][2], Al[ks][3], uWl + off);
        }
    }
    float acc[8][4];
#pragma unroll
    for (int nt = 0; nt < 8; ++nt)
        acc[nt][0] = acc[nt][1] = acc[nt][2] = acc[nt][3] = 0.f;

#pragma unroll
    for (int nt = 0; nt < 8; ++nt) {
        const uint32_t colb = nt * 16;
#pragma unroll
        for (int cb = 0; cb < 4; ++cb) {
            uint32_t b0, b1, b2, b3;
            ldsm4t(b0, b1, b2, b3, uBh + (cb * 32 + lane) * PB64_STRIDE + colb);
            mma16816(acc[nt], Ah[2*cb][0], Ah[2*cb][1], Ah[2*cb][2], Ah[2*cb][3], b0, b1);
            mma16816(acc[nt], Ah[2*cb+1][0], Ah[2*cb+1][1], Ah[2*cb+1][2], Ah[2*cb+1][3], b2, b3);
        }
#pragma unroll
        for (int cb = 0; cb < 4; ++cb) {
            uint32_t b0, b1, b2, b3;
            ldsm4t(b0, b1, b2, b3, uBl + (cb * 32 + lane) * PB64_STRIDE + colb);
            mma16816(acc[nt], Ah[2*cb][0], Ah[2*cb][1], Ah[2*cb][2], Ah[2*cb][3], b0, b1);
            mma16816(acc[nt], Ah[2*cb+1][0], Ah[2*cb+1][1], Ah[2*cb+1][2], Ah[2*cb+1][3], b2, b3);
        }
#pragma unroll
        for (int cb = 0; cb < 4; ++cb) {
            uint32_t b0, b1, b2, b3;
            ldsm4t(b0, b1, b2, b3, uBh + (cb * 32 + lane) * PB64_STRIDE + colb);
            mma16816(acc[nt], Al[2*cb][0], Al[2*cb][1], Al[2*cb][2], Al[2*cb][3], b0, b1);
            mma16816(acc[nt], Al[2*cb+1][0], Al[2*cb+1][1], Al[2*cb+1][2], Al[2*cb+1][3], b2, b3);
        }
    }
    const int g = lane >> 2, tq = lane & 3;
    const int m0 = w * 16 + g, m1 = m0 + 8;
    const float bb0 = bo[m0], bb1 = bo[m1];
    float* og = out + (size_t)(b * CC) * NT;
#pragma unroll
    for (int nt = 0; nt < 8; ++nt) {
        const int n = n0 + nt * 8 + tq * 2;
        *(float2*)(og + (size_t)m0 * NT + n) = make_float2(acc[nt][0] + bb0, acc[nt][1] + bb0);
        *(float2*)(og + (size_t)m1 * NT + n) = make_float2(acc[nt][2] + bb1, acc[nt][3] + bb1);
    }
}

// =============================== colsum / normscale ==========================
__global__ void __launch_bounds__(256, 2) colsum_kernel(const float* __restrict__ cx)
{
    const int row = blockIdx.x;
    const float* p = cx + (size_t)row * NT;
    const int tid = threadIdx.x;
    __shared__ float red[8];
    float s = 0.f;
#pragma unroll
    for (int it = 0; it < 4; ++it) {
        float4 v = ((const float4*)p)[tid + it * 256];
        s += v.x + v.y + v.z + v.w;
    }
#pragma unroll
    for (int o = 16; o > 0; o >>= 1) s += __shfl_xor_sync(0xffffffffu, s, o);
    if ((tid & 31) == 0) red[tid >> 5] = s;
    __syncthreads();
    if (tid == 0)
        g_colsum[row] = red[0] + red[1] + red[2] + red[3] +
                        red[4] + red[5] + red[6] + red[7];
}

__global__ void __launch_bounds__(256, 2) normscale_kernel()
{
    const int row = blockIdx.x;
    const int yy = blockIdx.y;
    const int tid = threadIdx.x;
    __shared__ float red[1];

    if (tid < 32) {
        float s = g_nsq[yy][row][tid];
#pragma unroll
        for (int o = 16; o > 0; o >>= 1) s += __shfl_xor_sync(0xffffffffu, s, o);
        if (tid == 0) red[0] = s;
    }
    __syncthreads();
    const float scl = (yy == 0 ? SCALE_F : 1.0f) / fmaxf(sqrtf(red[0]), 1e-12f);
    uint32_t* p = (uint32_t*)((yy == 0 ? g_qb : g_kb) + (size_t)row * NT);
#pragma unroll
    for (int it = 0; it < 8; ++it) {
        uint32_t u = p[tid + it * 256];
        float lo = __uint_as_float(u << 16) * scl;
        float hi = __uint_as_float(u & 0xffff0000u) * scl;
        p[tid + it * 256] = packbf(lo, hi);
    }
}

// ===== Stage B: G[F,e] = phi^T [v;1] — bf16 partials out (proven core) =======
__global__ void __launch_bounds__(256, 3) stageB_kernel()
{
    extern __shared__ unsigned char sm[];
    unsigned char* Kt0 = sm;
    unsigned char* Kt1 = sm + 34 * TS;
    unsigned char* Vt0 = sm + 2 * 34 * TS;
    unsigned char* Vt1 = Vt0 + 40 * TS;

    const int tid = threadIdx.x, w = tid >> 5, lane = tid & 31;
    const int fb = blockIdx.x >> 4, js = blockIdx.x & 15;
    const int bh = blockIdx.y;
    const int cbase = (bh >> 2) * CC + (bh & 3) * DH;
    const __nv_bfloat16* kg = g_kb + (size_t)cbase * NT;
    const __nv_bfloat16* vg = g_vb + (size_t)cbase * NT;
    const int j0 = js * (NT / JSPLIT);

    const uint32_t ONE2 = packbf(1.f, 1.f);
    const int g = lane >> 2, tq = lane & 3;

    int aLo, bLo, aHi, bHi;
    fdec(fb * 128 + w * 16 + g, aLo, bLo);
    fdec(fb * 128 + w * 16 + g + 8, aHi, bHi);

    for (int i = tid; i < 2 * 64; i += 256) {
        unsigned char* Kb = (i >> 6) ? Kt1 : Kt0;
        unsigned char* Vb = (i >> 6) ? Vt1 : Vt0;
        const int c = i & 63;
        *(uint32_t*)(Kb + 32 * TS + c * 4) = ONE2;
        *(uint32_t*)(Kb + 33 * TS + c * 4) = 0u;
        *(uint32_t*)(Vb + 32 * TS + c * 4) = ONE2;
#pragma unroll
        for (int z = 33; z < 40; ++z) *(uint32_t*)(Vb + z * TS + c * 4) = 0u;
    }

    const uint32_t uK[2] = { smem_u32(Kt0), smem_u32(Kt1) };
    const uint32_t uV[2] = { smem_u32(Vt0), smem_u32(Vt1) };

    {
#pragma unroll
        for (int r = 0; r < 4; ++r) {
            const int idx = tid + r * 256;
            const int d = idx >> 5, pr = idx & 31;
            const int ch = pr & 15;
            if ((pr >> 4) == 0)
                cp16(uK[0] + d * TS + ch * 16, kg + (size_t)d * NT + j0 + ch * 8);
            else
                cp16(uV[0] + d * TS + ch * 16, vg + (size_t)d * NT + j0 + ch * 8);
        }
        asm volatile("cp.async.commit_group;" ::: "memory");
    }

    float acc[5][4];
#pragma unroll
    for (int nt = 0; nt < 5; ++nt)
        acc[nt][0] = acc[nt][1] = acc[nt][2] = acc[nt][3] = 0.f;

    const int lq = lane >> 3, lr = lane & 7;

    for (int t = 0; t < NT / JSPLIT / 128; ++t) {
        asm volatile("cp.async.wait_group 0;" ::: "memory");
        __syncthreads();

        if (t < NT / JSPLIT / 128 - 1) {
            const int nb = (t + 1) & 1;
            const int jn = j0 + (t + 1) * 128;
#pragma unroll
            for (int r = 0; r < 4; ++r) {
                const int idx = tid + r * 256;
                const int d = idx >> 5, pr = idx & 31;
                const int ch = pr & 15;
                if ((pr >> 4) == 0)
                    cp16(uK[nb] + d * TS + ch * 16, kg + (size_t)d * NT + jn + ch * 8);
                else
                    cp16(uV[nb] + d * TS + ch * 16, vg + (size_t)d * NT + jn + ch * 8);
            }
            asm volatile("cp.async.commit_group;" ::: "memory");
        }

        const unsigned char* Ks = (t & 1) ? Kt1 : Kt0;
        const unsigned char* rAlo = Ks + aLo * TS;
        const unsigned char* rBlo = Ks + bLo * TS;
        const unsigned char* rAhi = Ks + aHi * TS;
        const unsigned char* rBhi = Ks + bHi * TS;
        const uint32_t uVs = uV[t & 1];

#pragma unroll
        for (int ug = 0; ug < 4; ++ug) {
            uint32_t A0[4], A1[4];
            {
                const int cb0 = (ug * 32 + 2 * tq) * 2;
                A0[0] = bffma2(*(const uint32_t*)(rAlo + cb0),
                               *(const uint32_t*)(rBlo + cb0), 0u);
                A0[1] = bffma2(*(const uint32_t*)(rAhi + cb0),
                               *(const uint32_t*)(rBhi + cb0), 0u);
                A0[2] = bffma2(*(const uint32_t*)(rAlo + cb0 + 16),
                               *(const uint32_t*)(rBlo + cb0 + 16), 0u);
                A0[3] = bffma2(*(const uint32_t*)(rAhi + cb0 + 16),
                               *(const uint32_t*)(rBhi + cb0 + 16), 0u);
                const int cb1 = cb0 + 32;
                A1[0] = bffma2(*(const uint32_t*)(rAlo + cb1),
                               *(const uint32_t*)(rBlo + cb1), 0u);
                A1[1] = bffma2(*(const uint32_t*)(rAhi + cb1),
                               *(const uint32_t*)(rBhi + cb1), 0u);
                A1[2] = bffma2(*(const uint32_t*)(rAlo + cb1 + 16),
                               *(const uint32_t*)(rBlo + cb1 + 16), 0u);
                A1[3] = bffma2(*(const uint32_t*)(rAhi + cb1 + 16),
                               *(const uint32_t*)(rBhi + cb1 + 16), 0u);
            }
#pragma unroll
            for (int nt = 0; nt < 5; ++nt) {
                uint32_t b0, b1, b2, b3;
                ldsm4(b0, b1, b2, b3,
                      uVs + (nt * 8 + lr) * TS + (ug * 4 + lq) * 16);
                mma16816(acc[nt], A0[0], A0[1], A0[2], A0[3], b0, b1);
                mma16816(acc[nt], A1[0], A1[1], A1[2], A1[3], b2, b3);
            }
        }
    }

    const int fr0 = fb * 128 + w * 16 + g, fr1 = fr0 + 8;
    __nv_bfloat16* Gp = g_G2 + (size_t)(bh * JSPLIT + js) * NE * NF;
#pragma unroll
    for (int nt = 0; nt < 5; ++nt) {
        const int e0 = nt * 8 + 2 * tq;
        Gp[(size_t)e0 * NF + fr0]       = __float2bfloat16_rn(acc[nt][0]);
        Gp[(size_t)(e0 + 1) * NF + fr0] = __float2bfloat16_rn(acc[nt][1]);
        Gp[(size_t)e0 * NF + fr1]       = __float2bfloat16_rn(acc[nt][2]);
        Gp[(size_t)(e0 + 1) * NF + fr1] = __float2bfloat16_rn(acc[nt][3]);
    }
}

// vectorized reduce: 4 f per thread, bf16 in/out, fp32 accumulate
__global__ void __launch_bounds__(256, 4) greduce_kernel()
{
    const int o = (blockIdx.x * 256 + threadIdx.x) * 4;   // < 8*NE*NF
    const int bh = o / (NE * NF);
    const int r = o - bh * (NE * NF);
    const int f = r % NF;
    const __nv_bfloat16* p = g_G2 + (size_t)bh * JSPLIT * NE * NF + r;
    float s0 = 0.f, s1 = 0.f, s2 = 0.f, s3 = 0.f;
#pragma unroll
    for (int js = 0; js < JSPLIT; ++js) {
        uint2 u = *(const uint2*)(p + (size_t)js * NE * NF);
        s0 += __uint_as_float(u.x << 16);
        s1 += __uint_as_float(u.x & 0xffff0000u);
        s2 += __uint_as_float(u.y << 16);
        s3 += __uint_as_float(u.y & 0xffff0000u);
    }
    s0 *= fweight(f);
    s1 *= fweight(f + 1);
    s2 *= fweight(f + 2);
    s3 *= fweight(f + 3);
    *(uint2*)(g_Gb + o) = make_uint2(packbf(s0, s1), packbf(s2, s3));
}

// ===================== Stage C: Odev = Psi(q) G + epilogue (proven) ==========
__global__ void __launch_bounds__(256, 2)
stageC_kernel(const float* __restrict__ Wv, const float* __restrict__ bv)
{
    extern __shared__ unsigned char sm[];
    unsigned char* Qt  = sm;
    unsigned char* Psi = Qt + 34 * TS;
    unsigned char* Gs  = Psi + 128 * TS;
    uint32_t* lut      = (uint32_t*)(Gs + NE * GSS);
    float* svs         = (float*)(lut + NF);
    float* rd          = svs + 32;

    const int tid = threadIdx.x, w = tid >> 5, lane = tid & 31;
    const int i0 = blockIdx.x * 128;
    const int bh = blockIdx.y;
    const int b = bh >> 2, hh = bh & 3;
    const int cbase = b * CC + hh * DH;
    const __nv_bfloat16* qg = g_qb + (size_t)cbase * NT;

    const uint32_t ONE2 = packbf(1.f, 1.f);
    build_lut(lut, tid);
    for (int c = tid; c < 64; c += 256) {
        *(uint32_t*)(Qt + 32 * TS + c * 4) = ONE2;
        *(uint32_t*)(Qt + 33 * TS + c * 4) = 0u;
    }

    const uint32_t uQt = smem_u32(Qt), uPsi = smem_u32(Psi), uGs = smem_u32(Gs);

    {
#pragma unroll
        for (int r = 0; r < 2; ++r) {
            const int idx = tid + r * 256;
            const int d = idx >> 4, ch = idx & 15;
            cp16(uQt + d * TS + ch * 16, qg + (size_t)d * NT + i0 + ch * 8);
        }
        const __nv_bfloat16* Gp = g_Gb + (size_t)bh * NE * NF;
        for (int idx = tid; idx < NE * (NF / 8); idx += 256) {
            const int e = idx / (NF / 8), c = idx % (NF / 8);
            cp16(uGs + e * GSS + c * 16, Gp + (size_t)e * NF + c * 8);
        }
        asm volatile("cp.async.commit_group;" ::: "memory");
        asm volatile("cp.async.wait_group 0;" ::: "memory");
    }
    __syncthreads();

    float acc[5][4];
#pragma unroll
    for (int nt = 0; nt < 5; ++nt)
        acc[nt][0] = acc[nt][1] = acc[nt][2] = acc[nt][3] = 0.f;

    const int lq = lane >> 3, lr = lane & 7;

    for (int fbi = 0; fbi < NFB; ++fbi) {
        if (fbi > 0) __syncthreads();
        {
#pragma unroll
            for (int r = 0; r < 16; ++r) {
                const int row = w * 16 + r;
                const uint32_t e = lut[fbi * 128 + row];
                const int a = e & 0xff, b2 = (e >> 8) & 0xff;
                uint2 qa = *(const uint2*)(Qt + a * TS + lane * 8);
                uint2 qb = *(const uint2*)(Qt + b2 * TS + lane * 8);
                uint2 ps;
                ps.x = bffma2(qa.x, qb.x, 0u);
                ps.y = bffma2(qa.y, qb.y, 0u);
                *(uint2*)(Psi + row * TS + lane * 8) = ps;
            }
        }
        __syncthreads();

#pragma unroll
        for (int ug = 0; ug < 4; ++ug) {
            uint32_t A0[4], A1[4];
            ldsm4t(A0[0], A0[1], A0[2], A0[3],
                   uPsi + ((2 * ug) * 16 + ((lane >> 4) << 3) + (lane & 7)) * TS
                        + (w * 16 + ((lane >> 3) & 1) * 8) * 2);
            ldsm4t(A1[0], A1[1], A1[2], A1[3],
                   uPsi + ((2 * ug + 1) * 16 + ((lane >> 4) << 3) + (lane & 7)) * TS
                        + (w * 16 + ((lane >> 3) & 1) * 8) * 2);
#pragma unroll
            for (int nt = 0; nt < 5; ++nt) {
                uint32_t b0, b1, b2, b3;
                ldsm4(b0, b1, b2, b3,
                      uGs + (nt * 8 + lr) * GSS + fbi * 256 + (ug * 4 + lq) * 16);
                mma16816(acc[nt], A0[0], A0[1], A0[2], A0[3], b0, b1);
                mma16816(acc[nt], A1[0], A1[1], A1[2], A1[3], b2, b3);
            }
        }
    }

    {
#pragma unroll
        for (int mi = 0; mi < 4; ++mi) {
            const int d = w * 4 + mi;
            const int m = hh * DH + d;
            float s = 0.f;
#pragma unroll
            for (int c4 = 0; c4 < 4; ++c4)
                s += Wv[m * 128 + c4 * 32 + lane] * g_colsum[b * CC + c4 * 32 + lane];
#pragma unroll
            for (int o = 16; o > 0; o >>= 1) s += __shfl_xor_sync(0xffffffffu, s, o);
            if (lane == 0) svs[d] = s + (float)NT * bv[m];
        }
    }
    const int g = lane >> 2, tq = lane & 3;
    if (tq == 0) {
        rd[w * 16 + g]     = acc[4][0];
        rd[w * 16 + g + 8] = acc[4][2];
    }
    __syncthreads();

    const int r0 = w * 16 + g, r1 = r0 + 8;
    const float inv0 = 1.0f / (4096.0f + rd[r0]);
    const float inv1 = 1.0f / (4096.0f + rd[r1]);
    float* att = g_att + (size_t)cbase * NT;
#pragma unroll
    for (int nt = 0; nt < 4; ++nt) {
        const int e0 = nt * 8 + 2 * tq;
        const float s0 = svs[e0], s1 = svs[e0 + 1];
        att[(size_t)e0 * NT + i0 + r0]       = (acc[nt][0] + s0) * inv0;
        att[(size_t)(e0 + 1) * NT + i0 + r0] = (acc[nt][1] + s1) * inv0;
        att[(size_t)e0 * NT + i0 + r1]       = (acc[nt][2] + s0) * inv1;
        att[(size_t)(e0 + 1) * NT + i0 + r1] = (acc[nt][3] + s1) * inv1;
    }
}

// ================================== launch ===================================
extern "C" void kernel_launch(void* const* d_in, const int* in_sizes, int n_in,
                              void* d_out, int out_size)
{
    (void)in_sizes; (void)n_in; (void)out_size;
    const float* x  = (const float*)d_in[0];
    const float* cx = (const float*)d_in[1];
    const float* Wq = (const float*)d_in[2];
    const float* bq = (const float*)d_in[3];
    const float* Wk = (const float*)d_in[4];
    const float* bk = (const float*)d_in[5];
    const float* Wv = (const float*)d_in[6];
    const float* bv = (const float*)d_in[7];
    const float* Wo = (const float*)d_in[8];
    const float* bo = (const float*)d_in[9];
    float* out = (float*)d_out;

    const int QKV_SMEM = 2 * 128 * PW_STRIDE;
    const int OUT_SMEM = 2 * 128 * PW_STRIDE + 2 * 128 * PB64_STRIDE;
    const int SB_SMEM  = 2 * 34 * TS + 2 * 40 * TS;
    const int SC_SMEM  = 34 * TS + 128 * TS + NE * GSS + NF * 4 + 160 * 4;

    cudaFuncSetAttribute(proj_qkv_mma, cudaFuncAttributeMaxDynamicSharedMemorySize, QKV_SMEM);
    cudaFuncSetAttribute(proj_out_mma, cudaFuncAttributeMaxDynamicSharedMemorySize, OUT_SMEM);
    cudaFuncSetAttribute(stageB_kernel, cudaFuncAttributeMaxDynamicSharedMemorySize, SB_SMEM);
    cudaFuncSetAttribute(stageC_kernel, cudaFuncAttributeMaxDynamicSharedMemorySize, SC_SMEM);

    proj_qkv_mma<<<dim3(NT / 128, BB, 3), 256, QKV_SMEM>>>(x, cx, Wq, bq, Wk, bk, Wv, bv);
    colsum_kernel<<<dim3(BB * CC), 256>>>(cx);
    normscale_kernel<<<dim3(BB * CC, 2), 256>>>();
    stageB_kernel<<<dim3(NFB * JSPLIT, BB * NH), 256, SB_SMEM>>>();   // 4th: profiled
    greduce_kernel<<<dim3(8 * NE * NF / 1024), 256>>>();
    stageC_kernel<<<dim3(NT / 128, BB * NH), 256, SC_SMEM>>>(Wv, bv);
    proj_out_mma<<<dim3(NT / 64, BB), 256, OUT_SMEM>>>(Wo, bo, out);
}

// round 17
// speedup vs baseline: 1.0421x; 1.0421x over previous
#include <cuda_runtime.h>
#include <cuda_bf16.h>
#include <cstdint>
#include <math.h>

#define BB 2
#define CC 128
#define NH 4
#define DH 32
#define NT 4096
#define SCALE_F 10.0f

#define NF 640
#define NFB 5
#define NE 40
#define TS 272
#define GSS 1296
#define JSPLIT 16

static __device__ __nv_bfloat16 g_qb[BB * CC * NT];
static __device__ __nv_bfloat16 g_kb[BB * CC * NT];
static __device__ __nv_bfloat16 g_vb[BB * CC * NT];
static __device__ float g_att[BB * CC * NT];
static __device__ float g_colsum[BB * CC];
static __device__ float g_nsq[2][BB * CC][32];
static __device__ float g_G2[8 * JSPLIT * NE * NF];
static __device__ __nv_bfloat16 g_Gb[8 * NE * NF];

// ---------------------------------------------------------------- helpers ----
__device__ __forceinline__ uint32_t smem_u32(const void* p) {
    uint32_t a;
    asm("{ .reg .u64 t; cvta.to.shared.u64 t, %1; cvt.u32.u64 %0, t; }"
        : "=r"(a) : "l"(p));
    return a;
}
__device__ __forceinline__ uint32_t packbf(float a, float b) {
    uint32_t r;
    asm("cvt.rn.bf16x2.f32 %0, %2, %1;" : "=r"(r) : "f"(a), "f"(b));
    return r;
}
__device__ __forceinline__ uint32_t bffma2(uint32_t a, uint32_t b, uint32_t c) {
    uint32_t d;
    asm("fma.rn.bf16x2 %0, %1, %2, %3;" : "=r"(d) : "r"(a), "r"(b), "r"(c));
    return d;
}
__device__ __forceinline__ void ldsm4(uint32_t& r0, uint32_t& r1, uint32_t& r2,
                                      uint32_t& r3, uint32_t addr) {
    asm volatile("ldmatrix.sync.aligned.m8n8.x4.shared.b16 {%0,%1,%2,%3}, [%4];"
                 : "=r"(r0), "=r"(r1), "=r"(r2), "=r"(r3) : "r"(addr));
}
__device__ __forceinline__ void ldsm4t(uint32_t& r0, uint32_t& r1, uint32_t& r2,
                                       uint32_t& r3, uint32_t addr) {
    asm volatile("ldmatrix.sync.aligned.m8n8.x4.trans.shared.b16 {%0,%1,%2,%3}, [%4];"
                 : "=r"(r0), "=r"(r1), "=r"(r2), "=r"(r3) : "r"(addr));
}
__device__ __forceinline__ void mma16816(float* c, uint32_t a0, uint32_t a1,
                                         uint32_t a2, uint32_t a3,
                                         uint32_t b0, uint32_t b1) {
    asm volatile(
        "mma.sync.aligned.m16n8k16.row.col.f32.bf16.bf16.f32 "
        "{%0,%1,%2,%3}, {%4,%5,%6,%7}, {%8,%9}, {%0,%1,%2,%3};"
        : "+f"(c[0]), "+f"(c[1]), "+f"(c[2]), "+f"(c[3])
        : "r"(a0), "r"(a1), "r"(a2), "r"(a3), "r"(b0), "r"(b1));
}
__device__ __forceinline__ void cp16(uint32_t dst, const void* src) {
    asm volatile("cp.async.cg.shared.global [%0], [%1], 16;"
                 :: "r"(dst), "l"(src) : "memory");
}

__device__ __forceinline__ void fdec(int f, int& a, int& b) {
    if (f < 32) { a = f; b = 32; }
    else if (f < 560) {
        int p = f - 32, aa = 0;
        while (p >= 32 - aa) { p -= 32 - aa; ++aa; }
        a = aa; b = aa + p;
    } else { a = 33; b = 33; }
}
__device__ __forceinline__ float fweight(int f) {
    if (f < 32) return 1.0f;
    if (f >= 560) return 0.0f;
    int a, b; fdec(f, a, b);
    return (a == b) ? 0.5f : 1.0f;
}
__device__ __forceinline__ void build_lut(uint32_t* lut, int tid) {
    for (int f = tid; f < NF; f += 256) {
        int a, b; fdec(f, a, b);
        lut[f] = (uint32_t)a | ((uint32_t)b << 8);
    }
}

// ============================= projections ===================================
#define PW_STRIDE 272
#define PB64_STRIDE 144

__global__ void __launch_bounds__(256, 2)
proj_qkv_mma(const float* __restrict__ x, const float* __restrict__ cx,
             const float* __restrict__ Wq, const float* __restrict__ bq,
             const float* __restrict__ Wk, const float* __restrict__ bk,
             const float* __restrict__ Wv, const float* __restrict__ bv)
{
    extern __shared__ unsigned char psm[];
    unsigned char* Wh = psm;
    unsigned char* Bh = psm + 128 * PW_STRIDE;

    const int tid = threadIdx.x, w = tid >> 5, lane = tid & 31;
    const int n0 = blockIdx.x * 128, b = blockIdx.y, wh = blockIdx.z;
    const float *W, *bias, *inb;
    if (wh == 0)      { W = Wq; bias = bq; inb = x  + (size_t)b * CC * NT; }
    else if (wh == 1) { W = Wk; bias = bk; inb = cx + (size_t)b * CC * NT; }
    else              { W = Wv; bias = bv; inb = cx + (size_t)b * CC * NT; }

#pragma unroll
    for (int it = 0; it < 16; ++it) {
        const int idx = tid + it * 256;
        const int m = idx >> 5, c4 = idx & 31;
        float4 ww = *(const float4*)(W + m * 128 + c4 * 4);
        *(uint2*)(Wh + m * PW_STRIDE + c4 * 8) =
            make_uint2(packbf(ww.x, ww.y), packbf(ww.z, ww.w));
    }
#pragma unroll
    for (int it = 0; it < 16; ++it) {
        const int idx = tid + it * 256;
        const int c = idx >> 5, c4 = idx & 31;
        float4 v = *(const float4*)(inb + (size_t)c * NT + n0 + c4 * 4);
        *(uint2*)(Bh + c * PW_STRIDE + c4 * 8) =
            make_uint2(packbf(v.x, v.y), packbf(v.z, v.w));
    }
    __syncthreads();

    const uint32_t uWh = smem_u32(Wh), uBh = smem_u32(Bh);
    uint32_t A[8][4];
    {
        const int q = lane >> 3, r = lane & 7;
#pragma unroll
        for (int ks = 0; ks < 8; ++ks)
            ldsm4(A[ks][0], A[ks][1], A[ks][2], A[ks][3],
                  uWh + (w * 16 + (q & 1) * 8 + r) * PW_STRIDE
                      + (ks * 16 + (q >> 1) * 8) * 2);
    }
    const int g = lane >> 2, tq = lane & 3;
    const int m0 = w * 16 + g, m1 = m0 + 8;
    const float bb0 = bias[m0], bb1 = bias[m1];
    float sq0 = 0.f, sq1 = 0.f;

    __nv_bfloat16* qkout = (wh == 0 ? g_qb : g_kb) + (size_t)(b * CC) * NT;
    __nv_bfloat16* vout  = g_vb + (size_t)(b * CC) * NT;

#pragma unroll
    for (int nh = 0; nh < 2; ++nh) {
        float acc[8][4];
#pragma unroll
        for (int nt = 0; nt < 8; ++nt)
            acc[nt][0] = acc[nt][1] = acc[nt][2] = acc[nt][3] = 0.f;
#pragma unroll
        for (int nt = 0; nt < 8; ++nt) {
            const uint32_t colb = nh * 128 + nt * 16;
#pragma unroll
            for (int cb = 0; cb < 4; ++cb) {
                uint32_t b0, b1, b2, b3;
                ldsm4t(b0, b1, b2, b3, uBh + (cb * 32 + lane) * PW_STRIDE + colb);
                mma16816(acc[nt], A[2*cb][0], A[2*cb][1], A[2*cb][2], A[2*cb][3], b0, b1);
                mma16816(acc[nt], A[2*cb+1][0], A[2*cb+1][1], A[2*cb+1][2], A[2*cb+1][3], b2, b3);
            }
        }
#pragma unroll
        for (int nt = 0; nt < 8; ++nt) {
            const int n = n0 + nh * 64 + nt * 8 + tq * 2;
            const float v0 = acc[nt][0] + bb0, v1 = acc[nt][1] + bb0;
            const float v2 = acc[nt][2] + bb1, v3 = acc[nt][3] + bb1;
            if (wh == 2) {
                *(uint32_t*)(vout + (size_t)m0 * NT + n) = packbf(v0, v1);
                *(uint32_t*)(vout + (size_t)m1 * NT + n) = packbf(v2, v3);
            } else {
                *(uint32_t*)(qkout + (size_t)m0 * NT + n) = packbf(v0, v1);
                *(uint32_t*)(qkout + (size_t)m1 * NT + n) = packbf(v2, v3);
                sq0 += v0 * v0 + v1 * v1;
                sq1 += v2 * v2 + v3 * v3;
            }
        }
    }
    if (wh < 2) {
        sq0 += __shfl_xor_sync(0xffffffffu, sq0, 1);
        sq0 += __shfl_xor_sync(0xffffffffu, sq0, 2);
        sq1 += __shfl_xor_sync(0xffffffffu, sq1, 1);
        sq1 += __shfl_xor_sync(0xffffffffu, sq1, 2);
        if (tq == 0) {
            g_nsq[wh][b * CC + m0][blockIdx.x] = sq0;
            g_nsq[wh][b * CC + m1][blockIdx.x] = sq1;
        }
    }
}

__global__ void __launch_bounds__(256, 2)
proj_out_mma(const float* __restrict__ Wo, const float* __restrict__ bo,
             float* __restrict__ out)
{
    extern __shared__ unsigned char psm[];
    unsigned char* Wh = psm;
    unsigned char* Wl = psm + 128 * PW_STRIDE;
    unsigned char* Bh = Wl + 128 * PW_STRIDE;
    unsigned char* Bl = Bh + 128 * PB64_STRIDE;

    const int tid = threadIdx.x, w = tid >> 5, lane = tid & 31;
    const int n0 = blockIdx.x * 64, b = blockIdx.y;
    const float* inb = g_att + (size_t)b * CC * NT;

#pragma unroll
    for (int it = 0; it < 16; ++it) {
        const int idx = tid + it * 256;
        const int m = idx >> 5, c4 = idx & 31;
        float4 ww = *(const float4*)(Wo + m * 128 + c4 * 4);
        uint32_t h0 = packbf(ww.x, ww.y), h1 = packbf(ww.z, ww.w);
        float l0 = ww.x - __uint_as_float(h0 << 16);
        float l1 = ww.y - __uint_as_float(h0 & 0xffff0000u);
        float l2 = ww.z - __uint_as_float(h1 << 16);
        float l3 = ww.w - __uint_as_float(h1 & 0xffff0000u);
        *(uint2*)(Wh + m * PW_STRIDE + c4 * 8) = make_uint2(h0, h1);
        *(uint2*)(Wl + m * PW_STRIDE + c4 * 8) =
            make_uint2(packbf(l0, l1), packbf(l2, l3));
    }
#pragma unroll
    for (int it = 0; it < 8; ++it) {
        const int idx = tid + it * 256;
        const int c = idx >> 4, c4 = idx & 15;
        float4 v = *(const float4*)(inb + (size_t)c * NT + n0 + c4 * 4);
        uint32_t h0 = packbf(v.x, v.y), h1 = packbf(v.z, v.w);
        float l0 = v.x - __uint_as_float(h0 << 16);
        float l1 = v.y - __uint_as_float(h0 & 0xffff0000u);
        float l2 = v.z - __uint_as_float(h1 << 16);
        float l3 = v.w - __uint_as_float(h1 & 0xffff0000u);
        *(uint2*)(Bh + c * PB64_STRIDE + c4 * 8) = make_uint2(h0, h1);
        *(uint2*)(Bl + c * PB64_STRIDE + c4 * 8) =
            make_uint2(packbf(l0, l1), packbf(l2, l3));
    }
    __syncthreads();

    const uint32_t uWh = smem_u32(Wh), uWl = smem_u32(Wl);
    const uint32_t uBh = smem_u32(Bh), uBl = smem_u32(Bl);
    uint32_t Ah[8][4], Al[8][4];
    {
        const int q = lane >> 3, r = lane & 7;
#pragma unroll
        for (int ks = 0; ks < 8; ++ks) {
            const uint32_t off = (w * 16 + (q & 1) * 8 + r) * PW_STRIDE
                               + (ks * 16 + (q >> 1) * 8) * 2;
            ldsm4(Ah[ks][0], Ah[ks][1], Ah[ks][2], Ah[ks][3], uWh + off);
            ldsm4(Al[ks][0], Al[ks][1], Al[ks][2], Al[ks][3], uWl + off);
        }
    }
    float acc[8][4];
#pragma unroll
    for (int nt = 0; nt < 8; ++nt)
        acc[nt][0] = acc[nt][1] = acc[nt][2] = acc[nt][3] = 0.f;

#pragma unroll
    for (int nt = 0; nt < 8; ++nt) {
        const uint32_t colb = nt * 16;
#pragma unroll
        for (int cb = 0; cb < 4; ++cb) {
            uint32_t b0, b1, b2, b3;
            ldsm4t(b0, b1, b2, b3, uBh + (cb * 32 + lane) * PB64_STRIDE + colb);
            mma16816(acc[nt], Ah[2*cb][0], Ah[2*cb][1], Ah[2*cb][2], Ah[2*cb][3], b0, b1);
            mma16816(acc[nt], Ah[2*cb+1][0], Ah[2*cb+1][1], Ah[2*cb+1][2], Ah[2*cb+1][3], b2, b3);
        }
#pragma unroll
        for (int cb = 0; cb < 4; ++cb) {
            uint32_t b0, b1, b2, b3;
            ldsm4t(b0, b1, b2, b3, uBl + (cb * 32 + lane) * PB64_STRIDE + colb);
            mma16816(acc[nt], Ah[2*cb][0], Ah[2*cb][1], Ah[2*cb][2], Ah[2*cb][3], b0, b1);
            mma16816(acc[nt], Ah[2*cb+1][0], Ah[2*cb+1][1], Ah[2*cb+1][2], Ah[2*cb+1][3], b2, b3);
        }
#pragma unroll
        for (int cb = 0; cb < 4; ++cb) {
            uint32_t b0, b1, b2, b3;
            ldsm4t(b0, b1, b2, b3, uBh + (cb * 32 + lane) * PB64_STRIDE + colb);
            mma16816(acc[nt], Al[2*cb][0], Al[2*cb][1], Al[2*cb][2], Al[2*cb][3], b0, b1);
            mma16816(acc[nt], Al[2*cb+1][0], Al[2*cb+1][1], Al[2*cb+1][2], Al[2*cb+1][3], b2, b3);
        }
    }
    const int g = lane >> 2, tq = lane & 3;
    const int m0 = w * 16 + g, m1 = m0 + 8;
    const float bb0 = bo[m0], bb1 = bo[m1];
    float* og = out + (size_t)(b * CC) * NT;
#pragma unroll
    for (int nt = 0; nt < 8; ++nt) {
        const int n = n0 + nt * 8 + tq * 2;
        *(float2*)(og + (size_t)m0 * NT + n) = make_float2(acc[nt][0] + bb0, acc[nt][1] + bb0);
        *(float2*)(og + (size_t)m1 * NT + n) = make_float2(acc[nt][2] + bb1, acc[nt][3] + bb1);
    }
}

// ======== fused norm-scale (y=0 q, y=1 k) + colsum (y=2) =====================
__global__ void __launch_bounds__(256, 2) normcol_kernel(const float* __restrict__ cx)
{
    const int row = blockIdx.x;
    const int yy = blockIdx.y;
    const int tid = threadIdx.x;
    __shared__ float red[8];

    if (yy < 2) {
        if (tid < 32) {
            float s = g_nsq[yy][row][tid];
#pragma unroll
            for (int o = 16; o > 0; o >>= 1) s += __shfl_xor_sync(0xffffffffu, s, o);
            if (tid == 0) red[0] = s;
        }
        __syncthreads();
        const float scl = (yy == 0 ? SCALE_F : 1.0f) /
                          fmaxf(sqrtf(red[0]), 1e-12f);
        uint32_t* p = (uint32_t*)((yy == 0 ? g_qb : g_kb) + (size_t)row * NT);
#pragma unroll
        for (int it = 0; it < 8; ++it) {
            uint32_t u = p[tid + it * 256];
            float lo = __uint_as_float(u << 16) * scl;
            float hi = __uint_as_float(u & 0xffff0000u) * scl;
            p[tid + it * 256] = packbf(lo, hi);
        }
    } else {
        const float* p = cx + (size_t)row * NT;
        float s = 0.f;
#pragma unroll
        for (int it = 0; it < 4; ++it) {
            float4 v = ((const float4*)p)[tid + it * 256];
            s += v.x + v.y + v.z + v.w;
        }
#pragma unroll
        for (int o = 16; o > 0; o >>= 1) s += __shfl_xor_sync(0xffffffffu, s, o);
        if ((tid & 31) == 0) red[tid >> 5] = s;
        __syncthreads();
        if (tid == 0)
            g_colsum[row] = red[0] + red[1] + red[2] + red[3] +
                            red[4] + red[5] + red[6] + red[7];
    }
}

// ===== Stage B: G[F,e] = phi^T [v;1] — fp32 partials (proven R14) ============
__global__ void __launch_bounds__(256, 3) stageB_kernel()
{
    extern __shared__ unsigned char sm[];
    unsigned char* Kt0 = sm;
    unsigned char* Kt1 = sm + 34 * TS;
    unsigned char* Vt0 = sm + 2 * 34 * TS;
    unsigned char* Vt1 = Vt0 + 40 * TS;

    const int tid = threadIdx.x, w = tid >> 5, lane = tid & 31;
    const int fb = blockIdx.x >> 4, js = blockIdx.x & 15;
    const int bh = blockIdx.y;
    const int cbase = (bh >> 2) * CC + (bh & 3) * DH;
    const __nv_bfloat16* kg = g_kb + (size_t)cbase * NT;
    const __nv_bfloat16* vg = g_vb + (size_t)cbase * NT;
    const int j0 = js * (NT / JSPLIT);

    const uint32_t ONE2 = packbf(1.f, 1.f);
    const int g = lane >> 2, tq = lane & 3;

    int aLo, bLo, aHi, bHi;
    fdec(fb * 128 + w * 16 + g, aLo, bLo);
    fdec(fb * 128 + w * 16 + g + 8, aHi, bHi);

    for (int i = tid; i < 2 * 64; i += 256) {
        unsigned char* Kb = (i >> 6) ? Kt1 : Kt0;
        unsigned char* Vb = (i >> 6) ? Vt1 : Vt0;
        const int c = i & 63;
        *(uint32_t*)(Kb + 32 * TS + c * 4) = ONE2;
        *(uint32_t*)(Kb + 33 * TS + c * 4) = 0u;
        *(uint32_t*)(Vb + 32 * TS + c * 4) = ONE2;
#pragma unroll
        for (int z = 33; z < 40; ++z) *(uint32_t*)(Vb + z * TS + c * 4) = 0u;
    }

    const uint32_t uK[2] = { smem_u32(Kt0), smem_u32(Kt1) };
    const uint32_t uV[2] = { smem_u32(Vt0), smem_u32(Vt1) };

    {
#pragma unroll
        for (int r = 0; r < 4; ++r) {
            const int idx = tid + r * 256;
            const int d = idx >> 5, pr = idx & 31;
            const int ch = pr & 15;
            if ((pr >> 4) == 0)
                cp16(uK[0] + d * TS + ch * 16, kg + (size_t)d * NT + j0 + ch * 8);
            else
                cp16(uV[0] + d * TS + ch * 16, vg + (size_t)d * NT + j0 + ch * 8);
        }
        asm volatile("cp.async.commit_group;" ::: "memory");
    }

    float acc[5][4];
#pragma unroll
    for (int nt = 0; nt < 5; ++nt)
        acc[nt][0] = acc[nt][1] = acc[nt][2] = acc[nt][3] = 0.f;

    const int lq = lane >> 3, lr = lane & 7;

    for (int t = 0; t < NT / JSPLIT / 128; ++t) {
        asm volatile("cp.async.wait_group 0;" ::: "memory");
        __syncthreads();

        if (t < NT / JSPLIT / 128 - 1) {
            const int nb = (t + 1) & 1;
            const int jn = j0 + (t + 1) * 128;
#pragma unroll
            for (int r = 0; r < 4; ++r) {
                const int idx = tid + r * 256;
                const int d = idx >> 5, pr = idx & 31;
                const int ch = pr & 15;
                if ((pr >> 4) == 0)
                    cp16(uK[nb] + d * TS + ch * 16, kg + (size_t)d * NT + jn + ch * 8);
                else
                    cp16(uV[nb] + d * TS + ch * 16, vg + (size_t)d * NT + jn + ch * 8);
            }
            asm volatile("cp.async.commit_group;" ::: "memory");
        }

        const unsigned char* Ks = (t & 1) ? Kt1 : Kt0;
        const unsigned char* rAlo = Ks + aLo * TS;
        const unsigned char* rBlo = Ks + bLo * TS;
        const unsigned char* rAhi = Ks + aHi * TS;
        const unsigned char* rBhi = Ks + bHi * TS;
        const uint32_t uVs = uV[t & 1];

#pragma unroll
        for (int ug = 0; ug < 4; ++ug) {
            uint32_t A0[4], A1[4];
            {
                const int cb0 = (ug * 32 + 2 * tq) * 2;
                A0[0] = bffma2(*(const uint32_t*)(rAlo + cb0),
                               *(const uint32_t*)(rBlo + cb0), 0u);
                A0[1] = bffma2(*(const uint32_t*)(rAhi + cb0),
                               *(const uint32_t*)(rBhi + cb0), 0u);
                A0[2] = bffma2(*(const uint32_t*)(rAlo + cb0 + 16),
                               *(const uint32_t*)(rBlo + cb0 + 16), 0u);
                A0[3] = bffma2(*(const uint32_t*)(rAhi + cb0 + 16),
                               *(const uint32_t*)(rBhi + cb0 + 16), 0u);
                const int cb1 = cb0 + 32;
                A1[0] = bffma2(*(const uint32_t*)(rAlo + cb1),
                               *(const uint32_t*)(rBlo + cb1), 0u);
                A1[1] = bffma2(*(const uint32_t*)(rAhi + cb1),
                               *(const uint32_t*)(rBhi + cb1), 0u);
                A1[2] = bffma2(*(const uint32_t*)(rAlo + cb1 + 16),
                               *(const uint32_t*)(rBlo + cb1 + 16), 0u);
                A1[3] = bffma2(*(const uint32_t*)(rAhi + cb1 + 16),
                               *(const uint32_t*)(rBhi + cb1 + 16), 0u);
            }
#pragma unroll
            for (int nt = 0; nt < 5; ++nt) {
                uint32_t b0, b1, b2, b3;
                ldsm4(b0, b1, b2, b3,
                      uVs + (nt * 8 + lr) * TS + (ug * 4 + lq) * 16);
                mma16816(acc[nt], A0[0], A0[1], A0[2], A0[3], b0, b1);
                mma16816(acc[nt], A1[0], A1[1], A1[2], A1[3], b2, b3);
            }
        }
    }

    const int fr0 = fb * 128 + w * 16 + g, fr1 = fr0 + 8;
    float* Gp = g_G2 + (size_t)(bh * JSPLIT + js) * NE * NF;
#pragma unroll
    for (int nt = 0; nt < 5; ++nt) {
        const int e0 = nt * 8 + 2 * tq;
        Gp[(size_t)e0 * NF + fr0]       = acc[nt][0];
        Gp[(size_t)(e0 + 1) * NF + fr0] = acc[nt][1];
        Gp[(size_t)e0 * NF + fr1]       = acc[nt][2];
        Gp[(size_t)(e0 + 1) * NF + fr1] = acc[nt][3];
    }
}

// vectorized reduce: 4 consecutive f per thread, float4 loads, fp32 accumulate
__global__ void __launch_bounds__(256, 4) greduce_kernel()
{
    const int o = (blockIdx.x * 256 + threadIdx.x) * 4;   // < 8*NE*NF
    const int bh = o / (NE * NF);
    const int r = o - bh * (NE * NF);
    const int f = r % NF;
    const float* p = g_G2 + (size_t)bh * JSPLIT * NE * NF + r;
    float s0 = 0.f, s1 = 0.f, s2 = 0.f, s3 = 0.f;
#pragma unroll
    for (int js = 0; js < JSPLIT; ++js) {
        float4 u = *(const float4*)(p + (size_t)js * NE * NF);
        s0 += u.x; s1 += u.y; s2 += u.z; s3 += u.w;
    }
    s0 *= fweight(f);
    s1 *= fweight(f + 1);
    s2 *= fweight(f + 2);
    s3 *= fweight(f + 3);
    *(uint2*)(g_Gb + o) = make_uint2(packbf(s0, s1), packbf(s2, s3));
}

// ===================== Stage C: Odev = Psi(q) G + epilogue (proven) ==========
__global__ void __launch_bounds__(256, 2)
stageC_kernel(const float* __restrict__ Wv, const float* __restrict__ bv)
{
    extern __shared__ unsigned char sm[];
    unsigned char* Qt  = sm;
    unsigned char* Psi = Qt + 34 * TS;
    unsigned char* Gs  = Psi + 128 * TS;
    uint32_t* lut      = (uint32_t*)(Gs + NE * GSS);
    float* svs         = (float*)(lut + NF);
    float* rd          = svs + 32;

    const int tid = threadIdx.x, w = tid >> 5, lane = tid & 31;
    const int i0 = blockIdx.x * 128;
    const int bh = blockIdx.y;
    const int b = bh >> 2, hh = bh & 3;
    const int cbase = b * CC + hh * DH;
    const __nv_bfloat16* qg = g_qb + (size_t)cbase * NT;

    const uint32_t ONE2 = packbf(1.f, 1.f);
    build_lut(lut, tid);
    for (int c = tid; c < 64; c += 256) {
        *(uint32_t*)(Qt + 32 * TS + c * 4) = ONE2;
        *(uint32_t*)(Qt + 33 * TS + c * 4) = 0u;
    }

    const uint32_t uQt = smem_u32(Qt), uPsi = smem_u32(Psi), uGs = smem_u32(Gs);

    {
#pragma unroll
        for (int r = 0; r < 2; ++r) {
            const int idx = tid + r * 256;
            const int d = idx >> 4, ch = idx & 15;
            cp16(uQt + d * TS + ch * 16, qg + (size_t)d * NT + i0 + ch * 8);
        }
        const __nv_bfloat16* Gp = g_Gb + (size_t)bh * NE * NF;
        for (int idx = tid; idx < NE * (NF / 8); idx += 256) {
            const int e = idx / (NF / 8), c = idx % (NF / 8);
            cp16(uGs + e * GSS + c * 16, Gp + (size_t)e * NF + c * 8);
        }
        asm volatile("cp.async.commit_group;" ::: "memory");
        asm volatile("cp.async.wait_group 0;" ::: "memory");
    }
    __syncthreads();

    float acc[5][4];
#pragma unroll
    for (int nt = 0; nt < 5; ++nt)
        acc[nt][0] = acc[nt][1] = acc[nt][2] = acc[nt][3] = 0.f;

    const int lq = lane >> 3, lr = lane & 7;

    for (int fbi = 0; fbi < NFB; ++fbi) {
        if (fbi > 0) __syncthreads();
        {
#pragma unroll
            for (int r = 0; r < 16; ++r) {
                const int row = w * 16 + r;
                const uint32_t e = lut[fbi * 128 + row];
                const int a = e & 0xff, b2 = (e >> 8) & 0xff;
                uint2 qa = *(const uint2*)(Qt + a * TS + lane * 8);
                uint2 qb = *(const uint2*)(Qt + b2 * TS + lane * 8);
                uint2 ps;
                ps.x = bffma2(qa.x, qb.x, 0u);
                ps.y = bffma2(qa.y, qb.y, 0u);
                *(uint2*)(Psi + row * TS + lane * 8) = ps;
            }
        }
        __syncthreads();

#pragma unroll
        for (int ug = 0; ug < 4; ++ug) {
            uint32_t A0[4], A1[4];
            ldsm4t(A0[0], A0[1], A0[2], A0[3],
                   uPsi + ((2 * ug) * 16 + ((lane >> 4) << 3) + (lane & 7)) * TS
                        + (w * 16 + ((lane >> 3) & 1) * 8) * 2);
            ldsm4t(A1[0], A1[1], A1[2], A1[3],
                   uPsi + ((2 * ug + 1) * 16 + ((lane >> 4) << 3) + (lane & 7)) * TS
                        + (w * 16 + ((lane >> 3) & 1) * 8) * 2);
#pragma unroll
            for (int nt = 0; nt < 5; ++nt) {
                uint32_t b0, b1, b2, b3;
                ldsm4(b0, b1, b2, b3,
                      uGs + (nt * 8 + lr) * GSS + fbi * 256 + (ug * 4 + lq) * 16);
                mma16816(acc[nt], A0[0], A0[1], A0[2], A0[3], b0, b1);
                mma16816(acc[nt], A1[0], A1[1], A1[2], A1[3], b2, b3);
            }
        }
    }

    {
#pragma unroll
        for (int mi = 0; mi < 4; ++mi) {
            const int d = w * 4 + mi;
            const int m = hh * DH + d;
            float s = 0.f;
#pragma unroll
            for (int c4 = 0; c4 < 4; ++c4)
                s += Wv[m * 128 + c4 * 32 + lane] * g_colsum[b * CC + c4 * 32 + lane];
#pragma unroll
            for (int o = 16; o > 0; o >>= 1) s += __shfl_xor_sync(0xffffffffu, s, o);
            if (lane == 0) svs[d] = s + (float)NT * bv[m];
        }
    }
    const int g = lane >> 2, tq = lane & 3;
    if (tq == 0) {
        rd[w * 16 + g]     = acc[4][0];
        rd[w * 16 + g + 8] = acc[4][2];
    }
    __syncthreads();

    const int r0 = w * 16 + g, r1 = r0 + 8;
    const float inv0 = 1.0f / (4096.0f + rd[r0]);
    const float inv1 = 1.0f / (4096.0f + rd[r1]);
    float* att = g_att + (size_t)cbase * NT;
#pragma unroll
    for (int nt = 0; nt < 4; ++nt) {
        const int e0 = nt * 8 + 2 * tq;
        const float s0 = svs[e0], s1 = svs[e0 + 1];
        att[(size_t)e0 * NT + i0 + r0]       = (acc[nt][0] + s0) * inv0;
        att[(size_t)(e0 + 1) * NT + i0 + r0] = (acc[nt][1] + s1) * inv0;
        att[(size_t)e0 * NT + i0 + r1]       = (acc[nt][2] + s0) * inv1;
        att[(size_t)(e0 + 1) * NT + i0 + r1] = (acc[nt][3] + s1) * inv1;
    }
}

// ================================== launch ===================================
extern "C" void kernel_launch(void* const* d_in, const int* in_sizes, int n_in,
                              void* d_out, int out_size)
{
    (void)in_sizes; (void)n_in; (void)out_size;
    const float* x  = (const float*)d_in[0];
    const float* cx = (const float*)d_in[1];
    const float* Wq = (const float*)d_in[2];
    const float* bq = (const float*)d_in[3];
    const float* Wk = (const float*)d_in[4];
    const float* bk = (const float*)d_in[5];
    const float* Wv = (const float*)d_in[6];
    const float* bv = (const float*)d_in[7];
    const float* Wo = (const float*)d_in[8];
    const float* bo = (const float*)d_in[9];
    float* out = (float*)d_out;

    const int QKV_SMEM = 2 * 128 * PW_STRIDE;
    const int OUT_SMEM = 2 * 128 * PW_STRIDE + 2 * 128 * PB64_STRIDE;
    const int SB_SMEM  = 2 * 34 * TS + 2 * 40 * TS;
    const int SC_SMEM  = 34 * TS + 128 * TS + NE * GSS + NF * 4 + 160 * 4;

    cudaFuncSetAttribute(proj_qkv_mma, cudaFuncAttributeMaxDynamicSharedMemorySize, QKV_SMEM);
    cudaFuncSetAttribute(proj_out_mma, cudaFuncAttributeMaxDynamicSharedMemorySize, OUT_SMEM);
    cudaFuncSetAttribute(stageB_kernel, cudaFuncAttributeMaxDynamicSharedMemorySize, SB_SMEM);
    cudaFuncSetAttribute(stageC_kernel, cudaFuncAttributeMaxDynamicSharedMemorySize, SC_SMEM);

    proj_qkv_mma<<<dim3(NT / 128, BB, 3), 256, QKV_SMEM>>>(x, cx, Wq, bq, Wk, bk, Wv, bv);
    normcol_kernel<<<dim3(BB * CC, 3), 256>>>(cx);
    stageB_kernel<<<dim3(NFB * JSPLIT, BB * NH), 256, SB_SMEM>>>();
    greduce_kernel<<<dim3(8 * NE * NF / 1024), 256>>>();   // 4th: profiled
    stageC_kernel<<<dim3(NT / 128, BB * NH), 256, SC_SMEM>>>(Wv, bv);
    proj_out_mma<<<dim3(NT / 64, BB), 256, OUT_SMEM>>>(Wo, bo, out);
}